// round 6
// baseline (speedup 1.0000x reference)
#include <cuda_runtime.h>

#define NN   2048
#define NN2  (NN*NN)
#define DT   0.01f
#define ITERS 5

// ---------------- device scratch (no cudaMalloc allowed) ----------------
__device__ float g_ku[NN2];
__device__ float g_kv[NN2];
__device__ float g_bu[NN2];
__device__ float g_bv[NN2];
__device__ float g_b [NN2];
__device__ float g_pB[NN2];
__device__ float g_r1[1024*1024];
__device__ float g_r2[512*512];
__device__ float g_r3[256*256];
__device__ float g_r4[128*128];
__device__ float g_r5[64*64];
__device__ float g_w128[128*128];

// ---------------- helpers ----------------
__device__ __forceinline__ float ldz(const float* __restrict__ a, int i, int j) {
    return (i >= 0 && i < NN && j >= 0 && j < NN) ? a[i*NN + j] : 0.f;
}
__device__ __forceinline__ float lde(const float* __restrict__ a, int i, int j) {
    i = max(0, min(NN-1, i)); j = max(0, min(NN-1, j));
    return a[i*NN + j];
}
__device__ __forceinline__ float kcoef(float uc, float vc, float AD2,
                                       float ADx, float ADy, float k1v) {
    float num = 0.25f * fabsf(0.5f * (fabsf(uc) + fabsf(vc)) * AD2);
    float den = 0.001f + 0.5f * (fabsf(ADx) + fabsf(ADy));
    return fminf(num / den, k1v);
}

// ---------------- k-coefficient pass ----------------
__global__ void kK(const float* __restrict__ a, const float* __restrict__ b,
                   const float* __restrict__ k1,
                   float* __restrict__ kou, float* __restrict__ kov) {
    int j = blockIdx.x*blockDim.x + threadIdx.x;
    int i = blockIdx.y*blockDim.y + threadIdx.y;
    int ij = i*NN + j;
    float ac = a[ij], bc = b[ij];
    float an = ldz(a,i-1,j), as_ = ldz(a,i+1,j), aw = ldz(a,i,j-1), ae = ldz(a,i,j+1);
    float bn = ldz(b,i-1,j), bs_ = ldz(b,i+1,j), bw = ldz(b,i,j-1), be = ldz(b,i,j+1);
    float ADx_a = 0.5f*(ae - aw), ADy_a = 0.5f*(as_ - an), AD2_a = an+as_+aw+ae - 4.f*ac;
    float ADx_b = 0.5f*(be - bw), ADy_b = 0.5f*(bs_ - bn), AD2_b = bn+bs_+bw+be - 4.f*bc;
    float k1v = k1[ij];
    kou[ij] = kcoef(ac, bc, AD2_a, ADx_a, ADy_a, k1v);
    kov[ij] = kcoef(ac, bc, AD2_b, ADx_b, ADy_b, k1v);
}

// ---------------- predictor: b_u, b_v ----------------
__global__ void kA2(const float* __restrict__ u, const float* __restrict__ v,
                    const float* __restrict__ ku, const float* __restrict__ kv,
                    const float* __restrict__ p,
                    float* __restrict__ bu, float* __restrict__ bv) {
    int j = blockIdx.x*blockDim.x + threadIdx.x;
    int i = blockIdx.y*blockDim.y + threadIdx.y;
    int ij = i*NN + j;
    float uc = u[ij], vc = v[ij];
    float un = ldz(u,i-1,j), us_ = ldz(u,i+1,j), uw = ldz(u,i,j-1), ue = ldz(u,i,j+1);
    float vn = ldz(v,i-1,j), vs_ = ldz(v,i+1,j), vw = ldz(v,i,j-1), ve = ldz(v,i,j+1);
    float ADx_u = 0.5f*(ue - uw), ADy_u = 0.5f*(us_ - un), AD2_u = un+us_+uw+ue - 4.f*uc;
    float ADx_v = 0.5f*(ve - vw), ADy_v = 0.5f*(vs_ - vn), AD2_v = vn+vs_+vw+ve - 4.f*vc;
    float kuc = ku[ij];
    float kun = ldz(ku,i-1,j), kus = ldz(ku,i+1,j), kuw = ldz(ku,i,j-1), kue = ldz(ku,i,j+1);
    float kvc = kv[ij];
    float kvn = ldz(kv,i-1,j), kvs = ldz(kv,i+1,j), kvw = ldz(kv,i,j-1), kve = ldz(kv,i,j+1);
    float kx = 1.5f*( kuc*AD2_u
                    + (un*kun + us_*kus + uw*kuw + ue*kue - 4.f*uc*kuc)
                    - uc*(kun + kus + kuw + kue - 4.f*kuc) );
    float ky = 1.5f*( kvc*AD2_v
                    + (vn*kvn + vs_*kvs + vw*kvw + ve*kve - 4.f*vc*kvc)
                    - vc*(kvn + kvs + kvw + kve - 4.f*kvc) );
    float Grapx = DT*0.5f*(lde(p,i,j+1) - lde(p,i,j-1));
    float Grapy = DT*0.5f*(lde(p,i+1,j) - lde(p,i-1,j));
    bu[ij] = uc + 0.5f*DT*(kx - uc*ADx_u - vc*ADy_u) - Grapx;
    bv[ij] = vc + 0.5f*DT*(ky - uc*ADx_v - vc*ADy_v) - Grapy;
}

// ---------------- corrector: u*, v* ----------------
__global__ void kB2(const float* __restrict__ u,  const float* __restrict__ v,
                    const float* __restrict__ bu, const float* __restrict__ bv,
                    const float* __restrict__ ku, const float* __restrict__ kv,
                    const float* __restrict__ p,
                    const float* __restrict__ Fx, const float* __restrict__ Fy,
                    float* __restrict__ us, float* __restrict__ vs) {
    int j = blockIdx.x*blockDim.x + threadIdx.x;
    int i = blockIdx.y*blockDim.y + threadIdx.y;
    int ij = i*NN + j;
    float uc = u[ij], vc = v[ij];
    float buc = bu[ij], bvc = bv[ij];
    float bun = ldz(bu,i-1,j), bus = ldz(bu,i+1,j), buw = ldz(bu,i,j-1), bue = ldz(bu,i,j+1);
    float bvn = ldz(bv,i-1,j), bvs = ldz(bv,i+1,j), bvw = ldz(bv,i,j-1), bve = ldz(bv,i,j+1);
    float ADx_bu = 0.5f*(bue - buw), ADy_bu = 0.5f*(bus - bun), AD2_bu = bun+bus+buw+bue - 4.f*buc;
    float ADx_bv = 0.5f*(bve - bvw), ADy_bv = 0.5f*(bvs - bvn), AD2_bv = bvn+bvs+bvw+bve - 4.f*bvc;
    float kuc = ku[ij];
    float kun = ldz(ku,i-1,j), kus = ldz(ku,i+1,j), kuw = ldz(ku,i,j-1), kue = ldz(ku,i,j+1);
    float kvc = kv[ij];
    float kvn = ldz(kv,i-1,j), kvs = ldz(kv,i+1,j), kvw = ldz(kv,i,j-1), kve = ldz(kv,i,j+1);
    // product term uses ORIGINAL velocities
    float un = ldz(u,i-1,j), us_ = ldz(u,i+1,j), uw = ldz(u,i,j-1), ue = ldz(u,i,j+1);
    float vn = ldz(v,i-1,j), vs_ = ldz(v,i+1,j), vw = ldz(v,i,j-1), ve = ldz(v,i,j+1);
    float kx = 1.5f*( kuc*AD2_bu
                    + (un*kun + us_*kus + uw*kuw + ue*kue - 4.f*uc*kuc)
                    - buc*(kun + kus + kuw + kue - 4.f*kuc) );
    float ky = 1.5f*( kvc*AD2_bv
                    + (vn*kvn + vs_*kvs + vw*kvw + ve*kve - 4.f*vc*kvc)
                    - bvc*(kvn + kvs + kvw + kve - 4.f*kvc) );
    float Grapx = DT*0.5f*(lde(p,i,j+1) - lde(p,i,j-1));
    float Grapy = DT*0.5f*(lde(p,i+1,j) - lde(p,i-1,j));
    us[ij] = uc + DT*(kx - buc*ADx_bu - bvc*ADy_bu) - Grapx - Fx[ij]*DT;
    vs[ij] = vc + DT*(ky - buc*ADx_bv - bvc*ADy_bv) - Grapy - Fy[ij]*DT;
}

// ---------------- MG right-hand side ----------------
__global__ void kMGb(const float* __restrict__ us, const float* __restrict__ vs,
                     float* __restrict__ b) {
    int j = blockIdx.x*blockDim.x + threadIdx.x;
    int i = blockIdx.y*blockDim.y + threadIdx.y;
    int ij = i*NN + j;
    float div = 0.5f*(ldz(us,i,j+1) - ldz(us,i,j-1))
              + 0.5f*(ldz(vs,i+1,j) - ldz(vs,i-1,j));
    b[ij] = -div / DT;
}

// =================================================================
// kDown: fused residual + restrictions 2048 -> 1024/512/256/128.
// Each block handles a 64x64 fine tile; restriction is block-local.
// =================================================================
__global__ __launch_bounds__(256)
void kDown(const float* __restrict__ p, const float* __restrict__ b,
           float* __restrict__ r1, float* __restrict__ r2,
           float* __restrict__ r3, float* __restrict__ r4) {
    __shared__ float sp[66][67];
    __shared__ float s1[32][33];
    __shared__ float s2[16][17];
    __shared__ float s3[8][9];
    int tx = threadIdx.x, ty = threadIdx.y;          // 16x16
    int t = ty*16 + tx;
    int i0 = blockIdx.y*64, j0 = blockIdx.x*64;
    for (int idx = t; idx < 66*66; idx += 256) {
        int a = idx/66, c = idx%66;
        int gi = min(max(i0 - 1 + a, 0), NN-1);
        int gj = min(max(j0 - 1 + c, 0), NN-1);
        sp[a][c] = p[gi*NN + gj];
    }
    __syncthreads();
    #pragma unroll
    for (int q = 0; q < 4; q++) {
        int I = 2*ty + (q >> 1), J = 2*tx + (q & 1);   // r1-local 0..31
        float acc = 0.f;
        #pragma unroll
        for (int di = 0; di < 2; di++)
        #pragma unroll
        for (int dj = 0; dj < 2; dj++) {
            int fi = 2*I + di, fj = 2*J + dj;          // fine-local 0..63
            float lap = sp[fi][fj+1] + sp[fi+2][fj+1] + sp[fi+1][fj] + sp[fi+1][fj+2]
                      - 4.f*sp[fi+1][fj+1];
            acc += lap - b[(i0+fi)*NN + (j0+fj)];
        }
        float v = 0.25f*acc;
        s1[I][J] = v;
        r1[((i0>>1)+I)*1024 + (j0>>1)+J] = v;
    }
    __syncthreads();
    {
        int I = ty, J = tx;
        float v = 0.25f*(s1[2*I][2*J] + s1[2*I][2*J+1] + s1[2*I+1][2*J] + s1[2*I+1][2*J+1]);
        s2[I][J] = v;
        r2[((i0>>2)+I)*512 + (j0>>2)+J] = v;
    }
    __syncthreads();
    if (t < 64) {
        int I = t >> 3, J = t & 7;
        float v = 0.25f*(s2[2*I][2*J] + s2[2*I][2*J+1] + s2[2*I+1][2*J] + s2[2*I+1][2*J+1]);
        s3[I][J] = v;
        r3[((i0>>3)+I)*256 + (j0>>3)+J] = v;
    }
    __syncthreads();
    if (t < 16) {
        int I = t >> 2, J = t & 3;
        float v = 0.25f*(s3[2*I][2*J] + s3[2*I][2*J+1] + s3[2*I+1][2*J] + s3[2*I+1][2*J+1]);
        r4[((i0>>4)+I)*128 + (j0>>4)+J] = v;
    }
}

// smooth ((sum4 - r)/4) then 2x nearest upsample (smem helper for kCoarse)
__device__ __forceinline__ void smoothUp(const float* win, const float* r,
                                         float* wout, int s, int t) {
    for (int idx = t; idx < s*s; idx += 1024) {
        int I = idx / s, J = idx % s;
        float sum = 0.f;
        if (I > 0)     sum += win[idx - s];
        if (I < s - 1) sum += win[idx + s];
        if (J > 0)     sum += win[idx - 1];
        if (J < s - 1) sum += win[idx + 1];
        float ws = 0.25f*(sum - r[idx]);
        float* o = wout + (2*I)*(2*s) + 2*J;
        o[0] = ws; o[1] = ws; o[2*s] = ws; o[2*s + 1] = ws;
    }
}

// ---------------- coarse pyramid: restrict 128->2, upsweep 2->128, one block ----------------
__global__ void kCoarse(const float* __restrict__ r4, float* __restrict__ r5,
                        float* __restrict__ wout,
                        float* __restrict__ out_r, int writeR) {
    __shared__ float r6[1024], r7[256], r8[64], r9[16], r10[4];
    __shared__ float wA[4096], wB[4096];
    int t = threadIdx.x;
    for (int idx = t; idx < 64*64; idx += 1024) {
        int I = idx >> 6, J = idx & 63;
        const float* s = r4 + (2*I)*128 + 2*J;
        r5[idx] = 0.25f*(s[0] + s[1] + s[128] + s[129]);
    }
    __syncthreads();
    { int I = t >> 5, J = t & 31;
      const float* s = r5 + (2*I)*64 + 2*J;
      r6[t] = 0.25f*(s[0] + s[1] + s[64] + s[65]); }
    __syncthreads();
    if (t < 256) { int I = t >> 4, J = t & 15; const float* s = r6 + (2*I)*32 + 2*J;
                   r7[t] = 0.25f*(s[0] + s[1] + s[32] + s[33]); }
    __syncthreads();
    if (t < 64)  { int I = t >> 3, J = t & 7;  const float* s = r7 + (2*I)*16 + 2*J;
                   r8[t] = 0.25f*(s[0] + s[1] + s[16] + s[17]); }
    __syncthreads();
    if (t < 16)  { int I = t >> 2, J = t & 3;  const float* s = r8 + (2*I)*8 + 2*J;
                   r9[t] = 0.25f*(s[0] + s[1] + s[8] + s[9]); }
    __syncthreads();
    if (t < 4)   { int I = t >> 1, J = t & 1;  const float* s = r9 + (2*I)*4 + 2*J;
                   r10[t] = 0.25f*(s[0] + s[1] + s[4] + s[5]); }
    __syncthreads();
    if (writeR && t < 4) out_r[t] = r10[t];
    if (t < 4) { int I = t >> 1, J = t & 1; float ws = -0.25f*r10[t];
                 float* o = wA + (2*I)*4 + 2*J; o[0] = ws; o[1] = ws; o[4] = ws; o[5] = ws; }
    __syncthreads();
    smoothUp(wA, r9, wB, 4,  t); __syncthreads();
    smoothUp(wB, r8, wA, 8,  t); __syncthreads();
    smoothUp(wA, r7, wB, 16, t); __syncthreads();
    smoothUp(wB, r6, wA, 32, t); __syncthreads();
    smoothUp(wA, r5, wout, 64, t);   // -> 128x128 in global
}

// =================================================================
// kUpF: fused up-sweep 128->256->512->1024 + prolongation to 2048
//       + p correction + final Jacobi. One block per 32x32 p tile.
// =================================================================
__global__ __launch_bounds__(1024)
void kUpF(const float* __restrict__ pin, const float* __restrict__ w128,
          const float* __restrict__ r1, const float* __restrict__ r2,
          const float* __restrict__ r3, const float* __restrict__ r4,
          const float* __restrict__ b,
          float* __restrict__ pout, float* __restrict__ out_w, int writeW) {
    __shared__ float s128[6][7];
    __shared__ float m128[4][5];
    __shared__ float m256[6][7];
    __shared__ float m512[10][11];
    __shared__ float m1024[18][19];
    int tx = threadIdx.x, ty = threadIdx.y;
    int bi = blockIdx.y, bj = blockIdx.x;
    int t = ty*32 + tx;
    int B128r = 2*bi - 2,  B128c = 2*bj - 2;
    int C128r = 2*bi - 1,  C128c = 2*bj - 1;
    int C256r = 4*bi - 1,  C256c = 4*bj - 1;
    int C512r = 8*bi - 1,  C512c = 8*bj - 1;
    int C1024r = 16*bi - 1, C1024c = 16*bj - 1;

    if (t < 36) {
        int a = t/6, c = t%6;
        int gi = B128r + a, gj = B128c + c;
        s128[a][c] = (gi >= 0 && gi < 128 && gj >= 0 && gj < 128) ? w128[gi*128 + gj] : 0.f;
    }
    __syncthreads();
    if (t < 16) {
        int a = t >> 2, c = t & 3;
        int gi = C128r + a, gj = C128c + c;
        float v = 0.f;
        if (gi >= 0 && gi < 128 && gj >= 0 && gj < 128) {
            float sum = s128[gi-1-B128r][gj-B128c] + s128[gi+1-B128r][gj-B128c]
                      + s128[gi-B128r][gj-1-B128c] + s128[gi-B128r][gj+1-B128c];
            v = 0.25f*(sum - r4[gi*128 + gj]);
        }
        m128[a][c] = v;
    }
    __syncthreads();
    if (t < 36) {
        int a = t/6, c = t%6;
        int gi = C256r + a, gj = C256c + c;
        float v = 0.f;
        if (gi >= 0 && gi < 256 && gj >= 0 && gj < 256) {
            auto w = [&](int y, int x) -> float {
                if (y < 0 || y >= 256 || x < 0 || x >= 256) return 0.f;
                return m128[(y>>1) - C128r][(x>>1) - C128c];
            };
            float sum = w(gi-1,gj) + w(gi+1,gj) + w(gi,gj-1) + w(gi,gj+1);
            v = 0.25f*(sum - r3[gi*256 + gj]);
        }
        m256[a][c] = v;
    }
    __syncthreads();
    if (t < 100) {
        int a = t/10, c = t%10;
        int gi = C512r + a, gj = C512c + c;
        float v = 0.f;
        if (gi >= 0 && gi < 512 && gj >= 0 && gj < 512) {
            auto w = [&](int y, int x) -> float {
                if (y < 0 || y >= 512 || x < 0 || x >= 512) return 0.f;
                return m256[(y>>1) - C256r][(x>>1) - C256c];
            };
            float sum = w(gi-1,gj) + w(gi+1,gj) + w(gi,gj-1) + w(gi,gj+1);
            v = 0.25f*(sum - r2[gi*512 + gj]);
        }
        m512[a][c] = v;
    }
    __syncthreads();
    if (t < 324) {
        int a = t/18, c = t%18;
        int gi = C1024r + a, gj = C1024c + c;
        float v = 0.f;
        if (gi >= 0 && gi < 1024 && gj >= 0 && gj < 1024) {
            auto w = [&](int y, int x) -> float {
                if (y < 0 || y >= 1024 || x < 0 || x >= 1024) return 0.f;
                return m512[(y>>1) - C512r][(x>>1) - C512c];
            };
            float sum = w(gi-1,gj) + w(gi+1,gj) + w(gi,gj-1) + w(gi,gj+1);
            v = 0.25f*(sum - r1[gi*1024 + gj]);
        }
        m1024[a][c] = v;
    }
    __syncthreads();
    int i = bi*32 + ty, j = bj*32 + tx;
    auto pp = [&](int a, int c) -> float {
        a = max(0, min(NN-1, a)); c = max(0, min(NN-1, c));
        return pin[a*NN + c] - m1024[(a>>1) - C1024r][(c>>1) - C1024c];
    };
    float pn = 0.25f*( pp(i-1,j) + pp(i+1,j) + pp(i,j-1) + pp(i,j+1) - b[i*NN + j] );
    pout[i*NN + j] = pn;
    if (writeW) out_w[i*NN + j] = m1024[(i>>1) - C1024r][(j>>1) - C1024c];
}

// ---------------- final velocity correction ----------------
__global__ void kFinalUV(const float* __restrict__ p,
                         float* __restrict__ u, float* __restrict__ v) {
    int j = blockIdx.x*blockDim.x + threadIdx.x;
    int i = blockIdx.y*blockDim.y + threadIdx.y;
    int ij = i*NN + j;
    float gx = DT*0.5f*(lde(p,i,j+1) - lde(p,i,j-1));
    float gy = DT*0.5f*(lde(p,i+1,j) - lde(p,i-1,j));
    u[ij] -= gx;
    v[ij] -= gy;
}

extern "C" void kernel_launch(void* const* d_in, const int* in_sizes, int n_in,
                              void* d_out, int out_size) {
    (void)in_sizes; (void)n_in; (void)out_size;
    const float* u  = (const float*)d_in[0];
    const float* v  = (const float*)d_in[1];
    const float* p  = (const float*)d_in[2];
    const float* Fx = (const float*)d_in[3];
    const float* Fy = (const float*)d_in[4];
    const float* k1 = (const float*)d_in[5];
    float* out   = (float*)d_out;
    float* out_u = out;
    float* out_v = out + (size_t)NN2;
    float* out_p = out + 2*(size_t)NN2;
    float* out_w = out + 3*(size_t)NN2;
    float* out_r = out + 4*(size_t)NN2;

    float *ku, *kv, *bu, *bv, *bb, *pB, *r1, *r2, *r3, *r4, *r5, *w128;
    cudaGetSymbolAddress((void**)&ku, g_ku);
    cudaGetSymbolAddress((void**)&kv, g_kv);
    cudaGetSymbolAddress((void**)&bu, g_bu);
    cudaGetSymbolAddress((void**)&bv, g_bv);
    cudaGetSymbolAddress((void**)&bb, g_b);
    cudaGetSymbolAddress((void**)&pB, g_pB);
    cudaGetSymbolAddress((void**)&r1, g_r1);
    cudaGetSymbolAddress((void**)&r2, g_r2);
    cudaGetSymbolAddress((void**)&r3, g_r3);
    cudaGetSymbolAddress((void**)&r4, g_r4);
    cudaGetSymbolAddress((void**)&r5, g_r5);
    cudaGetSymbolAddress((void**)&w128, g_w128);

    dim3 blk(32, 8);
    dim3 grd(NN/32, NN/8);

    // momentum predictor / corrector (R4 unfused layout — measured faster)
    kK <<<grd, blk>>>(u, v, k1, ku, kv);
    kA2<<<grd, blk>>>(u, v, ku, kv, p, bu, bv);
    kK <<<grd, blk>>>(bu, bv, k1, ku, kv);
    kB2<<<grd, blk>>>(u, v, bu, bv, ku, kv, p, Fx, Fy, out_u, out_v);
    kMGb<<<grd, blk>>>(out_u, out_v, bb);

    // F-cycle: 3 kernels per iteration
    for (int it = 0; it < ITERS; ++it) {
        const float* pin = (it == 0) ? p : ((it & 1) ? (const float*)out_p : (const float*)pB);
        float*       pout = (it & 1) ? pB : out_p;
        int last = (it == ITERS - 1);
        kDown<<<dim3(32, 32), dim3(16, 16)>>>(pin, bb, r1, r2, r3, r4);
        kCoarse<<<1, 1024>>>(r4, r5, w128, out_r, last);
        kUpF<<<dim3(64, 64), dim3(32, 32)>>>(pin, w128, r1, r2, r3, r4, bb,
                                             pout, out_w, last);
    }

    kFinalUV<<<grd, blk>>>(out_p, out_u, out_v);
}

// round 7
// speedup vs baseline: 1.2517x; 1.2517x over previous
#include <cuda_runtime.h>

#define NN   2048
#define NN2  (NN*NN)
#define DT   0.01f
#define ITERS 5

// ---------------- device scratch (no cudaMalloc allowed) ----------------
__device__ float g_ku[NN2];
__device__ float g_kv[NN2];
__device__ float g_bu[NN2];
__device__ float g_bv[NN2];
__device__ float g_b [NN2];
__device__ float g_pB[NN2];
__device__ float g_r1[1024*1024];
__device__ float g_r2[512*512];
__device__ float g_r3[256*256];
__device__ float g_r4[128*128];
__device__ float g_r5[64*64];
__device__ float g_wa[1024*1024];
__device__ float g_wb[1024*1024];

// ---------------- scalar helpers ----------------
__device__ __forceinline__ float lde(const float* __restrict__ a, int i, int j) {
    i = max(0, min(NN-1, i)); j = max(0, min(NN-1, j));
    return a[(size_t)i*NN + j];
}
__device__ __forceinline__ float kcoef(float uc, float vc, float AD2,
                                       float ADx, float ADy, float k1v) {
    float num = 0.25f * fabsf(0.5f * (fabsf(uc) + fabsf(vc)) * AD2);
    float den = 0.001f + 0.5f * (fabsf(ADx) + fabsf(ADy));
    return fminf(num / den, k1v);
}

// ---------------- vector row helpers (4 points per thread) ----------------
__device__ __forceinline__ float4 ld4(const float* __restrict__ a, int i, int j4) {
    return *reinterpret_cast<const float4*>(a + (size_t)i*NN + j4);
}
// r[0..5] = a[i][j4-1 .. j4+4], zeros outside domain (rows & cols)
__device__ __forceinline__ void row6z(const float* __restrict__ a, int i, int j4, float* r) {
    if ((unsigned)i >= (unsigned)NN) {
        #pragma unroll
        for (int k = 0; k < 6; k++) r[k] = 0.f;
        return;
    }
    float4 c = ld4(a, i, j4);
    r[1] = c.x; r[2] = c.y; r[3] = c.z; r[4] = c.w;
    r[0] = (j4 > 0)      ? a[(size_t)i*NN + j4 - 1] : 0.f;
    r[5] = (j4 + 4 < NN) ? a[(size_t)i*NN + j4 + 4] : 0.f;
}
// r[0..3] = a[i][j4..j4+3], zeros if row outside
__device__ __forceinline__ void row4z(const float* __restrict__ a, int i, int j4, float* r) {
    if ((unsigned)i >= (unsigned)NN) { r[0]=r[1]=r[2]=r[3]=0.f; return; }
    float4 c = ld4(a, i, j4);
    r[0] = c.x; r[1] = c.y; r[2] = c.z; r[3] = c.w;
}
// edge-replicate variants (for p)
__device__ __forceinline__ void row6e(const float* __restrict__ a, int i, int j4, float* r) {
    i = max(0, min(NN-1, i));
    float4 c = ld4(a, i, j4);
    r[1] = c.x; r[2] = c.y; r[3] = c.z; r[4] = c.w;
    r[0] = a[(size_t)i*NN + max(j4 - 1, 0)];
    r[5] = a[(size_t)i*NN + min(j4 + 4, NN-1)];
}
__device__ __forceinline__ void row4e(const float* __restrict__ a, int i, int j4, float* r) {
    i = max(0, min(NN-1, i));
    float4 c = ld4(a, i, j4);
    r[0] = c.x; r[1] = c.y; r[2] = c.z; r[3] = c.w;
}

// =================== k-coefficient pass (float4) ===================
__global__ __launch_bounds__(256)
void kK4(const float* __restrict__ a, const float* __restrict__ b,
         const float* __restrict__ k1,
         float* __restrict__ kou, float* __restrict__ kov) {
    int j4 = (blockIdx.x*32 + threadIdx.x)*4;
    int i  = blockIdx.y*8 + threadIdx.y;
    size_t ij = (size_t)i*NN + j4;
    float ac[6], an[4], as_[4], bc[6], bn[4], bs_[4], kc[4];
    row6z(a, i,   j4, ac);
    row4z(a, i-1, j4, an);
    row4z(a, i+1, j4, as_);
    row6z(b, i,   j4, bc);
    row4z(b, i-1, j4, bn);
    row4z(b, i+1, j4, bs_);
    row4z(k1, i,  j4, kc);
    float ou[4], ov[4];
    #pragma unroll
    for (int k = 0; k < 4; k++) {
        float uc = ac[k+1], uw = ac[k], ue = ac[k+2], un = an[k], us = as_[k];
        float vc = bc[k+1], vw = bc[k], ve = bc[k+2], vn = bn[k], vs = bs_[k];
        float ADx_a = 0.5f*(ue - uw), ADy_a = 0.5f*(us - un), AD2_a = un+us+uw+ue - 4.f*uc;
        float ADx_b = 0.5f*(ve - vw), ADy_b = 0.5f*(vs - vn), AD2_b = vn+vs+vw+ve - 4.f*vc;
        ou[k] = kcoef(uc, vc, AD2_a, ADx_a, ADy_a, kc[k]);
        ov[k] = kcoef(uc, vc, AD2_b, ADx_b, ADy_b, kc[k]);
    }
    *reinterpret_cast<float4*>(kou + ij) = make_float4(ou[0], ou[1], ou[2], ou[3]);
    *reinterpret_cast<float4*>(kov + ij) = make_float4(ov[0], ov[1], ov[2], ov[3]);
}

// =================== predictor (float4) ===================
__global__ __launch_bounds__(256)
void kA24(const float* __restrict__ u, const float* __restrict__ v,
          const float* __restrict__ ku, const float* __restrict__ kv,
          const float* __restrict__ p,
          float* __restrict__ bu, float* __restrict__ bv) {
    int j4 = (blockIdx.x*32 + threadIdx.x)*4;
    int i  = blockIdx.y*8 + threadIdx.y;
    size_t ij = (size_t)i*NN + j4;
    float kx[4], ADx_u[4], ADy_u[4], uc4[4];
    {   // stage 1: u & ku
        float k6[6], kn[4], ks[4], u6[6], un[4], us[4];
        row6z(ku, i, j4, k6); row4z(ku, i-1, j4, kn); row4z(ku, i+1, j4, ks);
        row6z(u,  i, j4, u6); row4z(u,  i-1, j4, un); row4z(u,  i+1, j4, us);
        #pragma unroll
        for (int k = 0; k < 4; k++) {
            float uc = u6[k+1], uw = u6[k], ue = u6[k+2];
            float kuc = k6[k+1];
            float AD2 = un[k] + us[k] + uw + ue - 4.f*uc;
            float prod = un[k]*kn[k] + us[k]*ks[k] + uw*k6[k] + ue*k6[k+2] - 4.f*uc*kuc;
            float ksum = kn[k] + ks[k] + k6[k] + k6[k+2] - 4.f*kuc;
            kx[k] = 1.5f*(kuc*AD2 + prod - uc*ksum);
            ADx_u[k] = 0.5f*(ue - uw);
            ADy_u[k] = 0.5f*(us[k] - un[k]);
            uc4[k] = uc;
        }
    }
    float ky[4], ADx_v[4], ADy_v[4], vc4[4];
    {   // stage 2: v & kv
        float k6[6], kn[4], ks[4], v6[6], vn[4], vs[4];
        row6z(kv, i, j4, k6); row4z(kv, i-1, j4, kn); row4z(kv, i+1, j4, ks);
        row6z(v,  i, j4, v6); row4z(v,  i-1, j4, vn); row4z(v,  i+1, j4, vs);
        #pragma unroll
        for (int k = 0; k < 4; k++) {
            float vc = v6[k+1], vw = v6[k], ve = v6[k+2];
            float kvc = k6[k+1];
            float AD2 = vn[k] + vs[k] + vw + ve - 4.f*vc;
            float prod = vn[k]*kn[k] + vs[k]*ks[k] + vw*k6[k] + ve*k6[k+2] - 4.f*vc*kvc;
            float ksum = kn[k] + ks[k] + k6[k] + k6[k+2] - 4.f*kvc;
            ky[k] = 1.5f*(kvc*AD2 + prod - vc*ksum);
            ADx_v[k] = 0.5f*(ve - vw);
            ADy_v[k] = 0.5f*(vs[k] - vn[k]);
            vc4[k] = vc;
        }
    }
    float p6[6], pn4[4], ps4[4];
    row6e(p, i, j4, p6); row4e(p, i-1, j4, pn4); row4e(p, i+1, j4, ps4);
    float obu[4], obv[4];
    #pragma unroll
    for (int k = 0; k < 4; k++) {
        float Grapx = DT*0.5f*(p6[k+2] - p6[k]);
        float Grapy = DT*0.5f*(ps4[k] - pn4[k]);
        obu[k] = uc4[k] + 0.5f*DT*(kx[k] - uc4[k]*ADx_u[k] - vc4[k]*ADy_u[k]) - Grapx;
        obv[k] = vc4[k] + 0.5f*DT*(ky[k] - uc4[k]*ADx_v[k] - vc4[k]*ADy_v[k]) - Grapy;
    }
    *reinterpret_cast<float4*>(bu + ij) = make_float4(obu[0], obu[1], obu[2], obu[3]);
    *reinterpret_cast<float4*>(bv + ij) = make_float4(obv[0], obv[1], obv[2], obv[3]);
}

// =================== corrector (float4) ===================
__global__ __launch_bounds__(256)
void kB24(const float* __restrict__ u,  const float* __restrict__ v,
          const float* __restrict__ bu, const float* __restrict__ bv,
          const float* __restrict__ ku, const float* __restrict__ kv,
          const float* __restrict__ p,
          const float* __restrict__ Fx, const float* __restrict__ Fy,
          float* __restrict__ us, float* __restrict__ vs) {
    int j4 = (blockIdx.x*32 + threadIdx.x)*4;
    int i  = blockIdx.y*8 + threadIdx.y;
    size_t ij = (size_t)i*NN + j4;
    // stage 1: ku with ORIGINAL u (product term)
    float term_u[4], ksum_u[4], kuc4[4], uc4[4];
    {
        float k6[6], kn[4], ks[4], u6[6], un[4], usr[4];
        row6z(ku, i, j4, k6); row4z(ku, i-1, j4, kn); row4z(ku, i+1, j4, ks);
        row6z(u,  i, j4, u6); row4z(u,  i-1, j4, un); row4z(u,  i+1, j4, usr);
        #pragma unroll
        for (int k = 0; k < 4; k++) {
            float uc = u6[k+1], kuc = k6[k+1];
            term_u[k] = un[k]*kn[k] + usr[k]*ks[k] + u6[k]*k6[k] + u6[k+2]*k6[k+2] - 4.f*uc*kuc;
            ksum_u[k] = kn[k] + ks[k] + k6[k] + k6[k+2] - 4.f*kuc;
            kuc4[k] = kuc; uc4[k] = uc;
        }
    }
    // stage 2: kv with ORIGINAL v
    float term_v[4], ksum_v[4], kvc4[4], vc4[4];
    {
        float k6[6], kn[4], ks[4], v6[6], vn[4], vsr[4];
        row6z(kv, i, j4, k6); row4z(kv, i-1, j4, kn); row4z(kv, i+1, j4, ks);
        row6z(v,  i, j4, v6); row4z(v,  i-1, j4, vn); row4z(v,  i+1, j4, vsr);
        #pragma unroll
        for (int k = 0; k < 4; k++) {
            float vc = v6[k+1], kvc = k6[k+1];
            term_v[k] = vn[k]*kn[k] + vsr[k]*ks[k] + v6[k]*k6[k] + v6[k+2]*k6[k+2] - 4.f*vc*kvc;
            ksum_v[k] = kn[k] + ks[k] + k6[k] + k6[k+2] - 4.f*kvc;
            kvc4[k] = kvc; vc4[k] = vc;
        }
    }
    // stage 3: bu stencil
    float kx[4], buc4[4], ADx_bu[4], ADy_bu[4];
    {
        float b6[6], bn[4], bs[4];
        row6z(bu, i, j4, b6); row4z(bu, i-1, j4, bn); row4z(bu, i+1, j4, bs);
        #pragma unroll
        for (int k = 0; k < 4; k++) {
            float bc = b6[k+1], bw = b6[k], be = b6[k+2];
            float AD2 = bn[k] + bs[k] + bw + be - 4.f*bc;
            kx[k] = 1.5f*(kuc4[k]*AD2 + term_u[k] - bc*ksum_u[k]);
            buc4[k] = bc;
            ADx_bu[k] = 0.5f*(be - bw);
            ADy_bu[k] = 0.5f*(bs[k] - bn[k]);
        }
    }
    // stage 4: bv stencil
    float ky[4], bvc4[4], ADx_bv[4], ADy_bv[4];
    {
        float b6[6], bn[4], bs[4];
        row6z(bv, i, j4, b6); row4z(bv, i-1, j4, bn); row4z(bv, i+1, j4, bs);
        #pragma unroll
        for (int k = 0; k < 4; k++) {
            float bc = b6[k+1], bw = b6[k], be = b6[k+2];
            float AD2 = bn[k] + bs[k] + bw + be - 4.f*bc;
            ky[k] = 1.5f*(kvc4[k]*AD2 + term_v[k] - bc*ksum_v[k]);
            bvc4[k] = bc;
            ADx_bv[k] = 0.5f*(be - bw);
            ADy_bv[k] = 0.5f*(bs[k] - bn[k]);
        }
    }
    // stage 5: p gradient + forces + output
    float p6[6], pn4[4], ps4[4];
    row6e(p, i, j4, p6); row4e(p, i-1, j4, pn4); row4e(p, i+1, j4, ps4);
    float4 fx = ld4(Fx, i, j4), fy = ld4(Fy, i, j4);
    float fxa[4] = {fx.x, fx.y, fx.z, fx.w};
    float fya[4] = {fy.x, fy.y, fy.z, fy.w};
    float ous[4], ovs[4];
    #pragma unroll
    for (int k = 0; k < 4; k++) {
        float Grapx = DT*0.5f*(p6[k+2] - p6[k]);
        float Grapy = DT*0.5f*(ps4[k] - pn4[k]);
        ous[k] = uc4[k] + DT*(kx[k] - buc4[k]*ADx_bu[k] - bvc4[k]*ADy_bu[k]) - Grapx - fxa[k]*DT;
        ovs[k] = vc4[k] + DT*(ky[k] - buc4[k]*ADx_bv[k] - bvc4[k]*ADy_bv[k]) - Grapy - fya[k]*DT;
    }
    *reinterpret_cast<float4*>(us + ij) = make_float4(ous[0], ous[1], ous[2], ous[3]);
    *reinterpret_cast<float4*>(vs + ij) = make_float4(ovs[0], ovs[1], ovs[2], ovs[3]);
}

// =================== MG rhs (float4) ===================
__global__ __launch_bounds__(256)
void kMGb4(const float* __restrict__ usrc, const float* __restrict__ vsrc,
           float* __restrict__ b) {
    int j4 = (blockIdx.x*32 + threadIdx.x)*4;
    int i  = blockIdx.y*8 + threadIdx.y;
    size_t ij = (size_t)i*NN + j4;
    float u6[6], vn4[4], vs4[4];
    row6z(usrc, i, j4, u6);
    row4z(vsrc, i-1, j4, vn4);
    row4z(vsrc, i+1, j4, vs4);
    float ob[4];
    #pragma unroll
    for (int k = 0; k < 4; k++) {
        float div = 0.5f*(u6[k+2] - u6[k]) + 0.5f*(vs4[k] - vn4[k]);
        ob[k] = -div / DT;
    }
    *reinterpret_cast<float4*>(b + ij) = make_float4(ob[0], ob[1], ob[2], ob[3]);
}

// =================== final velocity correction (float4) ===================
__global__ __launch_bounds__(256)
void kFinalUV4(const float* __restrict__ p,
               float* __restrict__ u, float* __restrict__ v) {
    int j4 = (blockIdx.x*32 + threadIdx.x)*4;
    int i  = blockIdx.y*8 + threadIdx.y;
    size_t ij = (size_t)i*NN + j4;
    float p6[6], pn4[4], ps4[4];
    row6e(p, i, j4, p6); row4e(p, i-1, j4, pn4); row4e(p, i+1, j4, ps4);
    float4 uu = *reinterpret_cast<float4*>(u + ij);
    float4 vv = *reinterpret_cast<float4*>(v + ij);
    float ua[4] = {uu.x, uu.y, uu.z, uu.w};
    float va[4] = {vv.x, vv.y, vv.z, vv.w};
    #pragma unroll
    for (int k = 0; k < 4; k++) {
        ua[k] -= DT*0.5f*(p6[k+2] - p6[k]);
        va[k] -= DT*0.5f*(ps4[k] - pn4[k]);
    }
    *reinterpret_cast<float4*>(u + ij) = make_float4(ua[0], ua[1], ua[2], ua[3]);
    *reinterpret_cast<float4*>(v + ij) = make_float4(va[0], va[1], va[2], va[3]);
}

// =================== MG section (best-measured R4 structure) ===================
__global__ void kResRestrict(const float* __restrict__ p, const float* __restrict__ b,
                             float* __restrict__ r1) {
    int J = blockIdx.x*blockDim.x + threadIdx.x;
    int I = blockIdx.y*blockDim.y + threadIdx.y;
    float acc = 0.f;
    #pragma unroll
    for (int di = 0; di < 2; di++)
    #pragma unroll
    for (int dj = 0; dj < 2; dj++) {
        int i = 2*I + di, j = 2*J + dj;
        float s = lde(p,i-1,j) + lde(p,i+1,j) + lde(p,i,j-1) + lde(p,i,j+1);
        acc += s - 4.f*p[(size_t)i*NN + j] - b[(size_t)i*NN + j];
    }
    r1[I*1024 + J] = 0.25f*acc;
}

__global__ void kRestrict(const float* __restrict__ in, float* __restrict__ out, int sout) {
    int J = blockIdx.x*blockDim.x + threadIdx.x;
    int I = blockIdx.y*blockDim.y + threadIdx.y;
    if (I >= sout || J >= sout) return;
    int sin = 2*sout;
    const float* s = in + (2*I)*sin + 2*J;
    out[I*sout + J] = 0.25f*(s[0] + s[1] + s[sin] + s[sin+1]);
}

__device__ __forceinline__ void smoothUp(const float* win, const float* r,
                                         float* wout, int s, int t) {
    for (int idx = t; idx < s*s; idx += 1024) {
        int I = idx / s, J = idx % s;
        float sum = 0.f;
        if (I > 0)     sum += win[idx - s];
        if (I < s - 1) sum += win[idx + s];
        if (J > 0)     sum += win[idx - 1];
        if (J < s - 1) sum += win[idx + 1];
        float ws = 0.25f*(sum - r[idx]);
        float* o = wout + (2*I)*(2*s) + 2*J;
        o[0] = ws; o[1] = ws; o[2*s] = ws; o[2*s + 1] = ws;
    }
}

__global__ void kCoarse(const float* __restrict__ r5, float* __restrict__ wout,
                        float* __restrict__ out_r, int writeR) {
    __shared__ float r6[1024], r7[256], r8[64], r9[16], r10[4];
    __shared__ float wA[4096], wB[4096];
    int t = threadIdx.x;
    { int I = t >> 5, J = t & 31;
      const float* s = r5 + (2*I)*64 + 2*J;
      r6[t] = 0.25f*(s[0] + s[1] + s[64] + s[65]); }
    __syncthreads();
    if (t < 256) { int I = t >> 4, J = t & 15; const float* s = r6 + (2*I)*32 + 2*J;
                   r7[t] = 0.25f*(s[0] + s[1] + s[32] + s[33]); }
    __syncthreads();
    if (t < 64)  { int I = t >> 3, J = t & 7;  const float* s = r7 + (2*I)*16 + 2*J;
                   r8[t] = 0.25f*(s[0] + s[1] + s[16] + s[17]); }
    __syncthreads();
    if (t < 16)  { int I = t >> 2, J = t & 3;  const float* s = r8 + (2*I)*8 + 2*J;
                   r9[t] = 0.25f*(s[0] + s[1] + s[8] + s[9]); }
    __syncthreads();
    if (t < 4)   { int I = t >> 1, J = t & 1;  const float* s = r9 + (2*I)*4 + 2*J;
                   r10[t] = 0.25f*(s[0] + s[1] + s[4] + s[5]); }
    __syncthreads();
    if (writeR && t < 4) out_r[t] = r10[t];
    if (t < 4) { int I = t >> 1, J = t & 1; float ws = -0.25f*r10[t];
                 float* o = wA + (2*I)*4 + 2*J; o[0] = ws; o[1] = ws; o[4] = ws; o[5] = ws; }
    __syncthreads();
    smoothUp(wA, r9, wB, 4,  t); __syncthreads();
    smoothUp(wB, r8, wA, 8,  t); __syncthreads();
    smoothUp(wA, r7, wB, 16, t); __syncthreads();
    smoothUp(wB, r6, wA, 32, t); __syncthreads();
    smoothUp(wA, r5, wout, 64, t);   // -> 128x128 in global
}

__global__ void kUp(const float* __restrict__ win, const float* __restrict__ r,
                    float* __restrict__ wout, int s) {
    int J = blockIdx.x*blockDim.x + threadIdx.x;
    int I = blockIdx.y*blockDim.y + threadIdx.y;
    if (I >= s || J >= s) return;
    int id = I*s + J;
    float sum = 0.f;
    if (I > 0)     sum += win[id - s];
    if (I < s - 1) sum += win[id + s];
    if (J > 0)     sum += win[id - 1];
    if (J < s - 1) sum += win[id + 1];
    float ws = 0.25f*(sum - r[id]);
    float* o = wout + (2*I)*(2*s) + 2*J;
    o[0] = ws; o[1] = ws; o[2*s] = ws; o[2*s + 1] = ws;
}

__global__ void kPUpdate(const float* __restrict__ pin, const float* __restrict__ w1024,
                         const float* __restrict__ r1, const float* __restrict__ b,
                         float* __restrict__ pout, float* __restrict__ out_w, int writeW) {
    __shared__ float wsm[18][19];
    int tx = threadIdx.x, ty = threadIdx.y;
    int bi = blockIdx.y, bj = blockIdx.x;
    int Ib = bi*16 - 1, Jb = bj*16 - 1;
    int t = ty*32 + tx;
    if (t < 324) {
        int a = t / 18, c = t % 18;
        int Ic = Ib + a, Jc = Jb + c;
        float val = 0.f;
        if (Ic >= 0 && Ic < 1024 && Jc >= 0 && Jc < 1024) {
            int id = Ic*1024 + Jc;
            float sum = 0.f;
            if (Ic > 0)    sum += w1024[id - 1024];
            if (Ic < 1023) sum += w1024[id + 1024];
            if (Jc > 0)    sum += w1024[id - 1];
            if (Jc < 1023) sum += w1024[id + 1];
            val = 0.25f*(sum - r1[id]);
        }
        wsm[a][c] = val;
    }
    __syncthreads();
    int i = bi*32 + ty, j = bj*32 + tx;
    auto pp = [&](int a, int c) -> float {
        a = max(0, min(NN-1, a)); c = max(0, min(NN-1, c));
        return pin[(size_t)a*NN + c] - wsm[(a >> 1) - Ib][(c >> 1) - Jb];
    };
    float pn = 0.25f*( pp(i-1,j) + pp(i+1,j) + pp(i,j-1) + pp(i,j+1) - b[(size_t)i*NN + j] );
    pout[(size_t)i*NN + j] = pn;
    if (writeW) out_w[(size_t)i*NN + j] = wsm[(i >> 1) - Ib][(j >> 1) - Jb];
}

extern "C" void kernel_launch(void* const* d_in, const int* in_sizes, int n_in,
                              void* d_out, int out_size) {
    (void)in_sizes; (void)n_in; (void)out_size;
    const float* u  = (const float*)d_in[0];
    const float* v  = (const float*)d_in[1];
    const float* p  = (const float*)d_in[2];
    const float* Fx = (const float*)d_in[3];
    const float* Fy = (const float*)d_in[4];
    const float* k1 = (const float*)d_in[5];
    float* out   = (float*)d_out;
    float* out_u = out;
    float* out_v = out + (size_t)NN2;
    float* out_p = out + 2*(size_t)NN2;
    float* out_w = out + 3*(size_t)NN2;
    float* out_r = out + 4*(size_t)NN2;

    float *ku, *kv, *bu, *bv, *bb, *pB, *r1, *r2, *r3, *r4, *r5, *wa, *wb;
    cudaGetSymbolAddress((void**)&ku, g_ku);
    cudaGetSymbolAddress((void**)&kv, g_kv);
    cudaGetSymbolAddress((void**)&bu, g_bu);
    cudaGetSymbolAddress((void**)&bv, g_bv);
    cudaGetSymbolAddress((void**)&bb, g_b);
    cudaGetSymbolAddress((void**)&pB, g_pB);
    cudaGetSymbolAddress((void**)&r1, g_r1);
    cudaGetSymbolAddress((void**)&r2, g_r2);
    cudaGetSymbolAddress((void**)&r3, g_r3);
    cudaGetSymbolAddress((void**)&r4, g_r4);
    cudaGetSymbolAddress((void**)&r5, g_r5);
    cudaGetSymbolAddress((void**)&wa, g_wa);
    cudaGetSymbolAddress((void**)&wb, g_wb);

    dim3 blk(32, 8);
    dim3 grd(NN/32, NN/8);
    dim3 grd4(NN/128, NN/8);   // float4 kernels: 4 points/thread in x

    // momentum predictor / corrector (vectorized)
    kK4 <<<grd4, blk>>>(u, v, k1, ku, kv);
    kA24<<<grd4, blk>>>(u, v, ku, kv, p, bu, bv);
    kK4 <<<grd4, blk>>>(bu, bv, k1, ku, kv);
    kB24<<<grd4, blk>>>(u, v, bu, bv, ku, kv, p, Fx, Fy, out_u, out_v);
    kMGb4<<<grd4, blk>>>(out_u, out_v, bb);

    // F-cycle (best-measured structure); iter0 reads input p directly
    for (int it = 0; it < ITERS; ++it) {
        const float* pin = (it == 0) ? p : ((it & 1) ? (const float*)out_p : (const float*)pB);
        float*       pout = (it & 1) ? pB : out_p;
        int last = (it == ITERS - 1);
        kResRestrict<<<dim3(1024/32, 1024/8), blk>>>(pin, bb, r1);
        kRestrict<<<dim3(512/32, 512/8), blk>>>(r1, r2, 512);
        kRestrict<<<dim3(256/32, 256/8), blk>>>(r2, r3, 256);
        kRestrict<<<dim3(128/32, 128/8), blk>>>(r3, r4, 128);
        kRestrict<<<dim3(64/32,  64/8),  blk>>>(r4, r5, 64);
        kCoarse<<<1, 1024>>>(r5, wa, out_r, last);          // -> 128^2
        kUp<<<dim3(128/32, 128/8), blk>>>(wa, r4, wb, 128); // -> 256^2
        kUp<<<dim3(256/32, 256/8), blk>>>(wb, r3, wa, 256); // -> 512^2
        kUp<<<dim3(512/32, 512/8), blk>>>(wa, r2, wb, 512); // -> 1024^2
        kPUpdate<<<dim3(64, 64), dim3(32, 32)>>>(pin, wb, r1, bb, pout, out_w, last);
    }

    kFinalUV4<<<grd4, blk>>>(out_p, out_u, out_v);
}

// round 8
// speedup vs baseline: 1.4878x; 1.1886x over previous
#include <cuda_runtime.h>

#define NN   2048
#define NN2  (NN*NN)
#define DT   0.01f
#define ITERS 5

// ---------------- device scratch (no cudaMalloc allowed) ----------------
__device__ float g_ku[NN2];
__device__ float g_kv[NN2];
__device__ float g_bu[NN2];
__device__ float g_bv[NN2];
__device__ float g_b [NN2];
__device__ float g_pB[NN2];
__device__ float g_r1[1024*1024];
__device__ float g_r2[512*512];
__device__ float g_r3[256*256];
__device__ float g_r4[128*128];
__device__ float g_r5[64*64];
__device__ float g_wa[1024*1024];
__device__ float g_wb[1024*1024];

// ---------------- scalar helpers ----------------
__device__ __forceinline__ float kcoef(float uc, float vc, float AD2,
                                       float ADx, float ADy, float k1v) {
    float num = 0.25f * fabsf(0.5f * (fabsf(uc) + fabsf(vc)) * AD2);
    float den = 0.001f + 0.5f * (fabsf(ADx) + fabsf(ADy));
    return fminf(num / den, k1v);
}

// ---------------- vector row helpers (NN-wide arrays) ----------------
__device__ __forceinline__ float4 ld4(const float* __restrict__ a, int i, int j4) {
    return *reinterpret_cast<const float4*>(a + (size_t)i*NN + j4);
}
__device__ __forceinline__ void row6z(const float* __restrict__ a, int i, int j4, float* r) {
    if ((unsigned)i >= (unsigned)NN) {
        #pragma unroll
        for (int k = 0; k < 6; k++) r[k] = 0.f;
        return;
    }
    float4 c = ld4(a, i, j4);
    r[1] = c.x; r[2] = c.y; r[3] = c.z; r[4] = c.w;
    r[0] = (j4 > 0)      ? a[(size_t)i*NN + j4 - 1] : 0.f;
    r[5] = (j4 + 4 < NN) ? a[(size_t)i*NN + j4 + 4] : 0.f;
}
__device__ __forceinline__ void row4z(const float* __restrict__ a, int i, int j4, float* r) {
    if ((unsigned)i >= (unsigned)NN) { r[0]=r[1]=r[2]=r[3]=0.f; return; }
    float4 c = ld4(a, i, j4);
    r[0] = c.x; r[1] = c.y; r[2] = c.z; r[3] = c.w;
}
__device__ __forceinline__ void row6e(const float* __restrict__ a, int i, int j4, float* r) {
    i = max(0, min(NN-1, i));
    float4 c = ld4(a, i, j4);
    r[1] = c.x; r[2] = c.y; r[3] = c.z; r[4] = c.w;
    r[0] = a[(size_t)i*NN + max(j4 - 1, 0)];
    r[5] = a[(size_t)i*NN + min(j4 + 4, NN-1)];
}
__device__ __forceinline__ void row4e(const float* __restrict__ a, int i, int j4, float* r) {
    i = max(0, min(NN-1, i));
    float4 c = ld4(a, i, j4);
    r[0] = c.x; r[1] = c.y; r[2] = c.z; r[3] = c.w;
}
// generic-size (s-wide) zero-boundary rows
__device__ __forceinline__ void vrow6z(const float* __restrict__ a, int i, int j4, int s, float* r) {
    if ((unsigned)i >= (unsigned)s) {
        #pragma unroll
        for (int k = 0; k < 6; k++) r[k] = 0.f;
        return;
    }
    float4 c = *reinterpret_cast<const float4*>(a + (size_t)i*s + j4);
    r[1] = c.x; r[2] = c.y; r[3] = c.z; r[4] = c.w;
    r[0] = (j4 > 0)      ? a[(size_t)i*s + j4 - 1] : 0.f;
    r[5] = (j4 + 4 < s)  ? a[(size_t)i*s + j4 + 4] : 0.f;
}
__device__ __forceinline__ void vrow4z(const float* __restrict__ a, int i, int j4, int s, float* r) {
    if ((unsigned)i >= (unsigned)s) { r[0]=r[1]=r[2]=r[3]=0.f; return; }
    float4 c = *reinterpret_cast<const float4*>(a + (size_t)i*s + j4);
    r[0] = c.x; r[1] = c.y; r[2] = c.z; r[3] = c.w;
}
// 10-wide edge-replicated p row (for kResRestrict4): cols j2-1 .. j2+8
__device__ __forceinline__ void prow10e(const float* __restrict__ a, int i, int j2, float* r) {
    i = max(0, min(NN-1, i));
    float4 x = ld4(a, i, j2), y = ld4(a, i, j2+4);
    r[1]=x.x; r[2]=x.y; r[3]=x.z; r[4]=x.w;
    r[5]=y.x; r[6]=y.y; r[7]=y.z; r[8]=y.w;
    r[0] = a[(size_t)i*NN + max(j2-1, 0)];
    r[9] = a[(size_t)i*NN + min(j2+8, NN-1)];
}

// =================== k-coefficient pass (float4) ===================
__global__ __launch_bounds__(256)
void kK4(const float* __restrict__ a, const float* __restrict__ b,
         const float* __restrict__ k1,
         float* __restrict__ kou, float* __restrict__ kov) {
    int j4 = (blockIdx.x*32 + threadIdx.x)*4;
    int i  = blockIdx.y*8 + threadIdx.y;
    size_t ij = (size_t)i*NN + j4;
    float ac[6], an[4], as_[4], bc[6], bn[4], bs_[4], kc[4];
    row6z(a, i,   j4, ac);
    row4z(a, i-1, j4, an);
    row4z(a, i+1, j4, as_);
    row6z(b, i,   j4, bc);
    row4z(b, i-1, j4, bn);
    row4z(b, i+1, j4, bs_);
    row4z(k1, i,  j4, kc);
    float ou[4], ov[4];
    #pragma unroll
    for (int k = 0; k < 4; k++) {
        float uc = ac[k+1], uw = ac[k], ue = ac[k+2], un = an[k], us = as_[k];
        float vc = bc[k+1], vw = bc[k], ve = bc[k+2], vn = bn[k], vs = bs_[k];
        float ADx_a = 0.5f*(ue - uw), ADy_a = 0.5f*(us - un), AD2_a = un+us+uw+ue - 4.f*uc;
        float ADx_b = 0.5f*(ve - vw), ADy_b = 0.5f*(vs - vn), AD2_b = vn+vs+vw+ve - 4.f*vc;
        ou[k] = kcoef(uc, vc, AD2_a, ADx_a, ADy_a, kc[k]);
        ov[k] = kcoef(uc, vc, AD2_b, ADx_b, ADy_b, kc[k]);
    }
    *reinterpret_cast<float4*>(kou + ij) = make_float4(ou[0], ou[1], ou[2], ou[3]);
    *reinterpret_cast<float4*>(kov + ij) = make_float4(ov[0], ov[1], ov[2], ov[3]);
}

// =================== predictor (float4) ===================
__global__ __launch_bounds__(256)
void kA24(const float* __restrict__ u, const float* __restrict__ v,
          const float* __restrict__ ku, const float* __restrict__ kv,
          const float* __restrict__ p,
          float* __restrict__ bu, float* __restrict__ bv) {
    int j4 = (blockIdx.x*32 + threadIdx.x)*4;
    int i  = blockIdx.y*8 + threadIdx.y;
    size_t ij = (size_t)i*NN + j4;
    float kx[4], ADx_u[4], ADy_u[4], uc4[4];
    {
        float k6[6], kn[4], ks[4], u6[6], un[4], us[4];
        row6z(ku, i, j4, k6); row4z(ku, i-1, j4, kn); row4z(ku, i+1, j4, ks);
        row6z(u,  i, j4, u6); row4z(u,  i-1, j4, un); row4z(u,  i+1, j4, us);
        #pragma unroll
        for (int k = 0; k < 4; k++) {
            float uc = u6[k+1], uw = u6[k], ue = u6[k+2];
            float kuc = k6[k+1];
            float AD2 = un[k] + us[k] + uw + ue - 4.f*uc;
            float prod = un[k]*kn[k] + us[k]*ks[k] + uw*k6[k] + ue*k6[k+2] - 4.f*uc*kuc;
            float ksum = kn[k] + ks[k] + k6[k] + k6[k+2] - 4.f*kuc;
            kx[k] = 1.5f*(kuc*AD2 + prod - uc*ksum);
            ADx_u[k] = 0.5f*(ue - uw);
            ADy_u[k] = 0.5f*(us[k] - un[k]);
            uc4[k] = uc;
        }
    }
    float ky[4], ADx_v[4], ADy_v[4], vc4[4];
    {
        float k6[6], kn[4], ks[4], v6[6], vn[4], vs[4];
        row6z(kv, i, j4, k6); row4z(kv, i-1, j4, kn); row4z(kv, i+1, j4, ks);
        row6z(v,  i, j4, v6); row4z(v,  i-1, j4, vn); row4z(v,  i+1, j4, vs);
        #pragma unroll
        for (int k = 0; k < 4; k++) {
            float vc = v6[k+1], vw = v6[k], ve = v6[k+2];
            float kvc = k6[k+1];
            float AD2 = vn[k] + vs[k] + vw + ve - 4.f*vc;
            float prod = vn[k]*kn[k] + vs[k]*ks[k] + vw*k6[k] + ve*k6[k+2] - 4.f*vc*kvc;
            float ksum = kn[k] + ks[k] + k6[k] + k6[k+2] - 4.f*kvc;
            ky[k] = 1.5f*(kvc*AD2 + prod - vc*ksum);
            ADx_v[k] = 0.5f*(ve - vw);
            ADy_v[k] = 0.5f*(vs[k] - vn[k]);
            vc4[k] = vc;
        }
    }
    float p6[6], pn4[4], ps4[4];
    row6e(p, i, j4, p6); row4e(p, i-1, j4, pn4); row4e(p, i+1, j4, ps4);
    float obu[4], obv[4];
    #pragma unroll
    for (int k = 0; k < 4; k++) {
        float Grapx = DT*0.5f*(p6[k+2] - p6[k]);
        float Grapy = DT*0.5f*(ps4[k] - pn4[k]);
        obu[k] = uc4[k] + 0.5f*DT*(kx[k] - uc4[k]*ADx_u[k] - vc4[k]*ADy_u[k]) - Grapx;
        obv[k] = vc4[k] + 0.5f*DT*(ky[k] - uc4[k]*ADx_v[k] - vc4[k]*ADy_v[k]) - Grapy;
    }
    *reinterpret_cast<float4*>(bu + ij) = make_float4(obu[0], obu[1], obu[2], obu[3]);
    *reinterpret_cast<float4*>(bv + ij) = make_float4(obv[0], obv[1], obv[2], obv[3]);
}

// =================== corrector (float4) ===================
__global__ __launch_bounds__(256)
void kB24(const float* __restrict__ u,  const float* __restrict__ v,
          const float* __restrict__ bu, const float* __restrict__ bv,
          const float* __restrict__ ku, const float* __restrict__ kv,
          const float* __restrict__ p,
          const float* __restrict__ Fx, const float* __restrict__ Fy,
          float* __restrict__ us, float* __restrict__ vs) {
    int j4 = (blockIdx.x*32 + threadIdx.x)*4;
    int i  = blockIdx.y*8 + threadIdx.y;
    size_t ij = (size_t)i*NN + j4;
    float term_u[4], ksum_u[4], kuc4[4], uc4[4];
    {
        float k6[6], kn[4], ks[4], u6[6], un[4], usr[4];
        row6z(ku, i, j4, k6); row4z(ku, i-1, j4, kn); row4z(ku, i+1, j4, ks);
        row6z(u,  i, j4, u6); row4z(u,  i-1, j4, un); row4z(u,  i+1, j4, usr);
        #pragma unroll
        for (int k = 0; k < 4; k++) {
            float uc = u6[k+1], kuc = k6[k+1];
            term_u[k] = un[k]*kn[k] + usr[k]*ks[k] + u6[k]*k6[k] + u6[k+2]*k6[k+2] - 4.f*uc*kuc;
            ksum_u[k] = kn[k] + ks[k] + k6[k] + k6[k+2] - 4.f*kuc;
            kuc4[k] = kuc; uc4[k] = uc;
        }
    }
    float term_v[4], ksum_v[4], kvc4[4], vc4[4];
    {
        float k6[6], kn[4], ks[4], v6[6], vn[4], vsr[4];
        row6z(kv, i, j4, k6); row4z(kv, i-1, j4, kn); row4z(kv, i+1, j4, ks);
        row6z(v,  i, j4, v6); row4z(v,  i-1, j4, vn); row4z(v,  i+1, j4, vsr);
        #pragma unroll
        for (int k = 0; k < 4; k++) {
            float vc = v6[k+1], kvc = k6[k+1];
            term_v[k] = vn[k]*kn[k] + vsr[k]*ks[k] + v6[k]*k6[k] + v6[k+2]*k6[k+2] - 4.f*vc*kvc;
            ksum_v[k] = kn[k] + ks[k] + k6[k] + k6[k+2] - 4.f*kvc;
            kvc4[k] = kvc; vc4[k] = vc;
        }
    }
    float kx[4], buc4[4], ADx_bu[4], ADy_bu[4];
    {
        float b6[6], bn[4], bs[4];
        row6z(bu, i, j4, b6); row4z(bu, i-1, j4, bn); row4z(bu, i+1, j4, bs);
        #pragma unroll
        for (int k = 0; k < 4; k++) {
            float bc = b6[k+1], bw = b6[k], be = b6[k+2];
            float AD2 = bn[k] + bs[k] + bw + be - 4.f*bc;
            kx[k] = 1.5f*(kuc4[k]*AD2 + term_u[k] - bc*ksum_u[k]);
            buc4[k] = bc;
            ADx_bu[k] = 0.5f*(be - bw);
            ADy_bu[k] = 0.5f*(bs[k] - bn[k]);
        }
    }
    float ky[4], bvc4[4], ADx_bv[4], ADy_bv[4];
    {
        float b6[6], bn[4], bs[4];
        row6z(bv, i, j4, b6); row4z(bv, i-1, j4, bn); row4z(bv, i+1, j4, bs);
        #pragma unroll
        for (int k = 0; k < 4; k++) {
            float bc = b6[k+1], bw = b6[k], be = b6[k+2];
            float AD2 = bn[k] + bs[k] + bw + be - 4.f*bc;
            ky[k] = 1.5f*(kvc4[k]*AD2 + term_v[k] - bc*ksum_v[k]);
            bvc4[k] = bc;
            ADx_bv[k] = 0.5f*(be - bw);
            ADy_bv[k] = 0.5f*(bs[k] - bn[k]);
        }
    }
    float p6[6], pn4[4], ps4[4];
    row6e(p, i, j4, p6); row4e(p, i-1, j4, pn4); row4e(p, i+1, j4, ps4);
    float4 fx = ld4(Fx, i, j4), fy = ld4(Fy, i, j4);
    float fxa[4] = {fx.x, fx.y, fx.z, fx.w};
    float fya[4] = {fy.x, fy.y, fy.z, fy.w};
    float ous[4], ovs[4];
    #pragma unroll
    for (int k = 0; k < 4; k++) {
        float Grapx = DT*0.5f*(p6[k+2] - p6[k]);
        float Grapy = DT*0.5f*(ps4[k] - pn4[k]);
        ous[k] = uc4[k] + DT*(kx[k] - buc4[k]*ADx_bu[k] - bvc4[k]*ADy_bu[k]) - Grapx - fxa[k]*DT;
        ovs[k] = vc4[k] + DT*(ky[k] - buc4[k]*ADx_bv[k] - bvc4[k]*ADy_bv[k]) - Grapy - fya[k]*DT;
    }
    *reinterpret_cast<float4*>(us + ij) = make_float4(ous[0], ous[1], ous[2], ous[3]);
    *reinterpret_cast<float4*>(vs + ij) = make_float4(ovs[0], ovs[1], ovs[2], ovs[3]);
}

// =================== MG rhs (float4) ===================
__global__ __launch_bounds__(256)
void kMGb4(const float* __restrict__ usrc, const float* __restrict__ vsrc,
           float* __restrict__ b) {
    int j4 = (blockIdx.x*32 + threadIdx.x)*4;
    int i  = blockIdx.y*8 + threadIdx.y;
    size_t ij = (size_t)i*NN + j4;
    float u6[6], vn4[4], vs4[4];
    row6z(usrc, i, j4, u6);
    row4z(vsrc, i-1, j4, vn4);
    row4z(vsrc, i+1, j4, vs4);
    float ob[4];
    #pragma unroll
    for (int k = 0; k < 4; k++) {
        float div = 0.5f*(u6[k+2] - u6[k]) + 0.5f*(vs4[k] - vn4[k]);
        ob[k] = -div / DT;
    }
    *reinterpret_cast<float4*>(b + ij) = make_float4(ob[0], ob[1], ob[2], ob[3]);
}

// =================== final velocity correction (float4) ===================
__global__ __launch_bounds__(256)
void kFinalUV4(const float* __restrict__ p,
               float* __restrict__ u, float* __restrict__ v) {
    int j4 = (blockIdx.x*32 + threadIdx.x)*4;
    int i  = blockIdx.y*8 + threadIdx.y;
    size_t ij = (size_t)i*NN + j4;
    float p6[6], pn4[4], ps4[4];
    row6e(p, i, j4, p6); row4e(p, i-1, j4, pn4); row4e(p, i+1, j4, ps4);
    float4 uu = *reinterpret_cast<float4*>(u + ij);
    float4 vv = *reinterpret_cast<float4*>(v + ij);
    float ua[4] = {uu.x, uu.y, uu.z, uu.w};
    float va[4] = {vv.x, vv.y, vv.z, vv.w};
    #pragma unroll
    for (int k = 0; k < 4; k++) {
        ua[k] -= DT*0.5f*(p6[k+2] - p6[k]);
        va[k] -= DT*0.5f*(ps4[k] - pn4[k]);
    }
    *reinterpret_cast<float4*>(u + ij) = make_float4(ua[0], ua[1], ua[2], ua[3]);
    *reinterpret_cast<float4*>(v + ij) = make_float4(va[0], va[1], va[2], va[3]);
}

// =================== residual + first restriction (float4) ===================
// each thread: 4 r1 outputs from an 8x2 fine region
__global__ __launch_bounds__(256)
void kResRestrict4(const float* __restrict__ p, const float* __restrict__ b,
                   float* __restrict__ r1) {
    int J4 = (blockIdx.x*32 + threadIdx.x)*4;   // r1 col base
    int I  = blockIdx.y*8 + threadIdx.y;        // r1 row
    int j2 = 2*J4;                              // fine col base
    int fi = 2*I;                               // fine row base
    float pr[4][10];
    prow10e(p, fi-1, j2, pr[0]);
    prow10e(p, fi,   j2, pr[1]);
    prow10e(p, fi+1, j2, pr[2]);
    prow10e(p, fi+2, j2, pr[3]);
    float4 b0a = ld4(b, fi,   j2), b0b = ld4(b, fi,   j2+4);
    float4 b1a = ld4(b, fi+1, j2), b1b = ld4(b, fi+1, j2+4);
    float brow[2][8] = {
        {b0a.x, b0a.y, b0a.z, b0a.w, b0b.x, b0b.y, b0b.z, b0b.w},
        {b1a.x, b1a.y, b1a.z, b1a.w, b1b.x, b1b.y, b1b.z, b1b.w}
    };
    float res[2][8];
    #pragma unroll
    for (int rr = 0; rr < 2; rr++)
    #pragma unroll
    for (int m = 0; m < 8; m++) {
        int r = rr + 1, c = m + 1;
        res[rr][m] = pr[r-1][c] + pr[r+1][c] + pr[r][c-1] + pr[r][c+1]
                   - 4.f*pr[r][c] - brow[rr][m];
    }
    float o[4];
    #pragma unroll
    for (int k = 0; k < 4; k++)
        o[k] = 0.25f*(res[0][2*k] + res[0][2*k+1] + res[1][2*k] + res[1][2*k+1]);
    *reinterpret_cast<float4*>(r1 + (size_t)I*1024 + J4) = make_float4(o[0], o[1], o[2], o[3]);
}

// =================== generic 2x restriction (float4) ===================
__global__ __launch_bounds__(256)
void kRestrict4(const float* __restrict__ in, float* __restrict__ out, int sout) {
    int J4 = (blockIdx.x*blockDim.x + threadIdx.x)*4;
    int I  = blockIdx.y*blockDim.y + threadIdx.y;
    if (I >= sout || J4 >= sout) return;
    int sin = 2*sout;
    const float* s0 = in + (size_t)(2*I)*sin + 2*J4;
    const float* s1 = s0 + sin;
    float4 a0 = *reinterpret_cast<const float4*>(s0);
    float4 a1 = *reinterpret_cast<const float4*>(s0 + 4);
    float4 c0 = *reinterpret_cast<const float4*>(s1);
    float4 c1 = *reinterpret_cast<const float4*>(s1 + 4);
    float4 o = make_float4(
        0.25f*(a0.x + a0.y + c0.x + c0.y),
        0.25f*(a0.z + a0.w + c0.z + c0.w),
        0.25f*(a1.x + a1.y + c1.x + c1.y),
        0.25f*(a1.z + a1.w + c1.z + c1.w));
    *reinterpret_cast<float4*>(out + (size_t)I*sout + J4) = o;
}

// =================== smooth+upsample (float4) ===================
__global__ __launch_bounds__(256)
void kUp4(const float* __restrict__ win, const float* __restrict__ r,
          float* __restrict__ wout, int s) {
    int J4 = (blockIdx.x*blockDim.x + threadIdx.x)*4;
    int I  = blockIdx.y*blockDim.y + threadIdx.y;
    if (I >= s || J4 >= s) return;
    float c6[6], n4[4], s4[4], r4_[4];
    vrow6z(win, I,   J4, s, c6);
    vrow4z(win, I-1, J4, s, n4);
    vrow4z(win, I+1, J4, s, s4);
    vrow4z(r,   I,   J4, s, r4_);
    float ws[4];
    #pragma unroll
    for (int k = 0; k < 4; k++)
        ws[k] = 0.25f*(n4[k] + s4[k] + c6[k] + c6[k+2] - r4_[k]);
    float4 lo = make_float4(ws[0], ws[0], ws[1], ws[1]);
    float4 hi = make_float4(ws[2], ws[2], ws[3], ws[3]);
    float* o0 = wout + (size_t)(2*I)*(2*s) + 2*J4;
    float* o1 = o0 + 2*s;
    *reinterpret_cast<float4*>(o0)     = lo;
    *reinterpret_cast<float4*>(o0 + 4) = hi;
    *reinterpret_cast<float4*>(o1)     = lo;
    *reinterpret_cast<float4*>(o1 + 4) = hi;
}

// ---------------- coarse pyramid: restrict 128->2, upsweep 2->128, one block ----------------
__device__ __forceinline__ void smoothUp(const float* win, const float* r,
                                         float* wout, int s, int t) {
    for (int idx = t; idx < s*s; idx += 1024) {
        int I = idx / s, J = idx % s;
        float sum = 0.f;
        if (I > 0)     sum += win[idx - s];
        if (I < s - 1) sum += win[idx + s];
        if (J > 0)     sum += win[idx - 1];
        if (J < s - 1) sum += win[idx + 1];
        float ws = 0.25f*(sum - r[idx]);
        float* o = wout + (2*I)*(2*s) + 2*J;
        o[0] = ws; o[1] = ws; o[2*s] = ws; o[2*s + 1] = ws;
    }
}

__global__ void kCoarse(const float* __restrict__ r4, float* __restrict__ r5,
                        float* __restrict__ wout,
                        float* __restrict__ out_r, int writeR) {
    __shared__ float r6[1024], r7[256], r8[64], r9[16], r10[4];
    __shared__ float wA[4096], wB[4096];
    int t = threadIdx.x;
    for (int idx = t; idx < 64*64; idx += 1024) {
        int I = idx >> 6, J = idx & 63;
        const float* s = r4 + (2*I)*128 + 2*J;
        r5[idx] = 0.25f*(s[0] + s[1] + s[128] + s[129]);
    }
    __syncthreads();
    { int I = t >> 5, J = t & 31;
      const float* s = r5 + (2*I)*64 + 2*J;
      r6[t] = 0.25f*(s[0] + s[1] + s[64] + s[65]); }
    __syncthreads();
    if (t < 256) { int I = t >> 4, J = t & 15; const float* s = r6 + (2*I)*32 + 2*J;
                   r7[t] = 0.25f*(s[0] + s[1] + s[32] + s[33]); }
    __syncthreads();
    if (t < 64)  { int I = t >> 3, J = t & 7;  const float* s = r7 + (2*I)*16 + 2*J;
                   r8[t] = 0.25f*(s[0] + s[1] + s[16] + s[17]); }
    __syncthreads();
    if (t < 16)  { int I = t >> 2, J = t & 3;  const float* s = r8 + (2*I)*8 + 2*J;
                   r9[t] = 0.25f*(s[0] + s[1] + s[8] + s[9]); }
    __syncthreads();
    if (t < 4)   { int I = t >> 1, J = t & 1;  const float* s = r9 + (2*I)*4 + 2*J;
                   r10[t] = 0.25f*(s[0] + s[1] + s[4] + s[5]); }
    __syncthreads();
    if (writeR && t < 4) out_r[t] = r10[t];
    if (t < 4) { int I = t >> 1, J = t & 1; float ws = -0.25f*r10[t];
                 float* o = wA + (2*I)*4 + 2*J; o[0] = ws; o[1] = ws; o[4] = ws; o[5] = ws; }
    __syncthreads();
    smoothUp(wA, r9, wB, 4,  t); __syncthreads();
    smoothUp(wB, r8, wA, 8,  t); __syncthreads();
    smoothUp(wA, r7, wB, 16, t); __syncthreads();
    smoothUp(wB, r6, wA, 32, t); __syncthreads();
    smoothUp(wA, r5, wout, 64, t);   // -> 128x128 in global
}

// =================== fused final prolongation + p update (float4) ===================
__global__ __launch_bounds__(256)
void kPUpdate4(const float* __restrict__ pin, const float* __restrict__ w1024,
               const float* __restrict__ r1, const float* __restrict__ b,
               float* __restrict__ pout, float* __restrict__ out_w, int writeW) {
    __shared__ float wsm[18][19];
    int tx = threadIdx.x, ty = threadIdx.y;   // (8, 32)
    int bi = blockIdx.y, bj = blockIdx.x;
    int Ib = bi*16 - 1, Jb = bj*16 - 1;
    int t = ty*8 + tx;
    for (int idx = t; idx < 324; idx += 256) {
        int a = idx / 18, c = idx % 18;
        int Ic = Ib + a, Jc = Jb + c;
        float val = 0.f;
        if (Ic >= 0 && Ic < 1024 && Jc >= 0 && Jc < 1024) {
            int id = Ic*1024 + Jc;
            float sum = 0.f;
            if (Ic > 0)    sum += w1024[id - 1024];
            if (Ic < 1023) sum += w1024[id + 1024];
            if (Jc > 0)    sum += w1024[id - 1];
            if (Jc < 1023) sum += w1024[id + 1];
            val = 0.25f*(sum - r1[id]);
        }
        wsm[a][c] = val;
    }
    __syncthreads();
    int i = bi*32 + ty;
    int j4 = bj*32 + tx*4;
    float p6[6], pn4[4], ps4[4];
    row6e(pin, i, j4, p6);
    row4e(pin, i-1, j4, pn4);
    row4e(pin, i+1, j4, ps4);
    float4 bb4 = ld4(b, i, j4);
    float ba[4] = {bb4.x, bb4.y, bb4.z, bb4.w};
    int wr  = (i >> 1) - Ib;
    int wrN = (max(i-1, 0) >> 1) - Ib;
    int wrS = (min(i+1, NN-1) >> 1) - Ib;
    float o[4], wv[4];
    #pragma unroll
    for (int k = 0; k < 4; k++) {
        int c  = j4 + k;
        int cc = (c >> 1) - Jb;
        int cw = (max(c-1, 0) >> 1) - Jb;
        int ce = (min(c+1, NN-1) >> 1) - Jb;
        float north = pn4[k]  - wsm[wrN][cc];
        float south = ps4[k]  - wsm[wrS][cc];
        float west  = p6[k]   - wsm[wr][cw];
        float east  = p6[k+2] - wsm[wr][ce];
        o[k] = 0.25f*(north + south + west + east - ba[k]);
        wv[k] = wsm[wr][cc];
    }
    size_t ij = (size_t)i*NN + j4;
    *reinterpret_cast<float4*>(pout + ij) = make_float4(o[0], o[1], o[2], o[3]);
    if (writeW)
        *reinterpret_cast<float4*>(out_w + ij) = make_float4(wv[0], wv[1], wv[2], wv[3]);
}

extern "C" void kernel_launch(void* const* d_in, const int* in_sizes, int n_in,
                              void* d_out, int out_size) {
    (void)in_sizes; (void)n_in; (void)out_size;
    const float* u  = (const float*)d_in[0];
    const float* v  = (const float*)d_in[1];
    const float* p  = (const float*)d_in[2];
    const float* Fx = (const float*)d_in[3];
    const float* Fy = (const float*)d_in[4];
    const float* k1 = (const float*)d_in[5];
    float* out   = (float*)d_out;
    float* out_u = out;
    float* out_v = out + (size_t)NN2;
    float* out_p = out + 2*(size_t)NN2;
    float* out_w = out + 3*(size_t)NN2;
    float* out_r = out + 4*(size_t)NN2;

    float *ku, *kv, *bu, *bv, *bb, *pB, *r1, *r2, *r3, *r4, *r5, *wa, *wb;
    cudaGetSymbolAddress((void**)&ku, g_ku);
    cudaGetSymbolAddress((void**)&kv, g_kv);
    cudaGetSymbolAddress((void**)&bu, g_bu);
    cudaGetSymbolAddress((void**)&bv, g_bv);
    cudaGetSymbolAddress((void**)&bb, g_b);
    cudaGetSymbolAddress((void**)&pB, g_pB);
    cudaGetSymbolAddress((void**)&r1, g_r1);
    cudaGetSymbolAddress((void**)&r2, g_r2);
    cudaGetSymbolAddress((void**)&r3, g_r3);
    cudaGetSymbolAddress((void**)&r4, g_r4);
    cudaGetSymbolAddress((void**)&r5, g_r5);
    cudaGetSymbolAddress((void**)&wa, g_wa);
    cudaGetSymbolAddress((void**)&wb, g_wb);

    dim3 blk(32, 8);
    dim3 grd4(NN/128, NN/8);   // float4 kernels: 4 points/thread in x

    // momentum predictor / corrector (vectorized)
    kK4 <<<grd4, blk>>>(u, v, k1, ku, kv);
    kA24<<<grd4, blk>>>(u, v, ku, kv, p, bu, bv);
    kK4 <<<grd4, blk>>>(bu, bv, k1, ku, kv);
    kB24<<<grd4, blk>>>(u, v, bu, bv, ku, kv, p, Fx, Fy, out_u, out_v);
    kMGb4<<<grd4, blk>>>(out_u, out_v, bb);

    // F-cycle (vectorized); iter0 reads input p directly
    for (int it = 0; it < ITERS; ++it) {
        const float* pin = (it == 0) ? p : ((it & 1) ? (const float*)out_p : (const float*)pB);
        float*       pout = (it & 1) ? pB : out_p;
        int last = (it == ITERS - 1);
        kResRestrict4<<<dim3(1024/128, 1024/8), blk>>>(pin, bb, r1);
        kRestrict4<<<dim3(512/128, 512/8), blk>>>(r1, r2, 512);
        kRestrict4<<<dim3(256/128, 256/8), blk>>>(r2, r3, 256);
        kRestrict4<<<dim3(1, 128/8), blk>>>(r3, r4, 128);
        kCoarse<<<1, 1024>>>(r4, r5, wa, out_r, last);        // 128->64->...->2->128
        kUp4<<<dim3(1, 128/8), blk>>>(wa, r4, wb, 128);       // -> 256^2
        kUp4<<<dim3(256/128, 256/8), blk>>>(wb, r3, wa, 256); // -> 512^2
        kUp4<<<dim3(512/128, 512/8), blk>>>(wa, r2, wb, 512); // -> 1024^2
        kPUpdate4<<<dim3(64, 64), dim3(8, 32)>>>(pin, wb, r1, bb, pout, out_w, last);
    }

    kFinalUV4<<<grd4, blk>>>(out_p, out_u, out_v);
}